// round 1
// baseline (speedup 1.0000x reference)
#include <cuda_runtime.h>
#include <cuda_bf16.h>

// Problem constants (fixed shapes per reference):
//   N_NODES = 8192, K_FRE = 2048 (N - K_FRE = 6144), D = 512
#define NN 8192
#define KF 2048
#define KH 6144   // NN - KF
#define DD 512

// Scratch (device globals; allocation inside kernel_launch is forbidden)
static __device__ float g_pre[NN * DD];   // x @ W            16 MB
static __device__ float g_t1 [KF * DD];   // s1 @ pre          4 MB
static __device__ float g_t3 [KH * DD];   // s3 @ pre         12 MB
static __device__ float g_low[NN * DD];   // a0*(s0 @ t1)     16 MB
static __device__ float g_alpha[2];       // softmax(alpha)

__global__ void softmax2_kernel(const float* __restrict__ alpha) {
    float a0 = alpha[0], a1 = alpha[1];
    float m  = fmaxf(a0, a1);
    float e0 = expf(a0 - m), e1 = expf(a1 - m);
    float inv = 1.0f / (e0 + e1);
    g_alpha[0] = e0 * inv;
    g_alpha[1] = e1 * inv;
}

// Tiled fp32 GEMM: C[M,N] = A[M,K] @ B[K,N], row-major.
// Block tile 128x64, K-tile 16, 256 threads, per-thread 8x4 accumulator.
// MODE 0: C = acc
// MODE 1: C = g_alpha[aidx] * acc
// MODE 2: C = relu( max(g_alpha[aidx]*acc, other) + bias[col] )
template<int MODE>
__global__ __launch_bounds__(256)
void gemm_tile(const float* __restrict__ A, const float* __restrict__ B,
               float* __restrict__ C, int M, int N, int K,
               int aidx, const float* __restrict__ other,
               const float* __restrict__ bias)
{
    __shared__ float As[16][128];   // transposed A tile: As[k][m]
    __shared__ float Bs[16][64];    // Bs[k][n]

    const int tid = threadIdx.x;
    const int tx  = tid & 15;       // 0..15 -> col group (4 cols each)
    const int ty  = tid >> 4;       // 0..15 -> row group (8 rows each)
    const int brow = blockIdx.y * 128;
    const int bcol = blockIdx.x * 64;

    // load mapping
    const int a_r  = tid >> 2;          // 0..63
    const int a_c4 = (tid & 3) * 4;     // 0,4,8,12
    const int b_r  = tid >> 4;          // 0..15
    const int b_c4 = (tid & 15) * 4;    // 0..60

    float acc[8][4];
    #pragma unroll
    for (int i = 0; i < 8; i++)
        #pragma unroll
        for (int j = 0; j < 4; j++) acc[i][j] = 0.0f;

    for (int kt = 0; kt < K; kt += 16) {
        // global loads (vectorized)
        float4 a0 = *reinterpret_cast<const float4*>(A + (size_t)(brow + a_r)      * K + kt + a_c4);
        float4 a1 = *reinterpret_cast<const float4*>(A + (size_t)(brow + a_r + 64) * K + kt + a_c4);
        float4 b0 = *reinterpret_cast<const float4*>(B + (size_t)(kt + b_r) * N + bcol + b_c4);

        __syncthreads();   // protect previous iteration's smem reads

        // store A transposed
        As[a_c4 + 0][a_r] = a0.x;  As[a_c4 + 1][a_r] = a0.y;
        As[a_c4 + 2][a_r] = a0.z;  As[a_c4 + 3][a_r] = a0.w;
        As[a_c4 + 0][a_r + 64] = a1.x;  As[a_c4 + 1][a_r + 64] = a1.y;
        As[a_c4 + 2][a_r + 64] = a1.z;  As[a_c4 + 3][a_r + 64] = a1.w;
        *reinterpret_cast<float4*>(&Bs[b_r][b_c4]) = b0;

        __syncthreads();

        #pragma unroll
        for (int k = 0; k < 16; k++) {
            float4 av0 = *reinterpret_cast<const float4*>(&As[k][ty * 8]);
            float4 av1 = *reinterpret_cast<const float4*>(&As[k][ty * 8 + 4]);
            float4 bv  = *reinterpret_cast<const float4*>(&Bs[k][tx * 4]);
            float a[8] = {av0.x, av0.y, av0.z, av0.w, av1.x, av1.y, av1.z, av1.w};
            float b[4] = {bv.x, bv.y, bv.z, bv.w};
            #pragma unroll
            for (int i = 0; i < 8; i++)
                #pragma unroll
                for (int j = 0; j < 4; j++)
                    acc[i][j] = fmaf(a[i], b[j], acc[i][j]);
        }
    }

    float scale = 1.0f;
    if (MODE >= 1) scale = g_alpha[aidx];

    #pragma unroll
    for (int i = 0; i < 8; i++) {
        const int row = brow + ty * 8 + i;
        const int col = bcol + tx * 4;
        float* Cp = C + (size_t)row * N + col;
        if (MODE == 0) {
            float4 v = {acc[i][0], acc[i][1], acc[i][2], acc[i][3]};
            *reinterpret_cast<float4*>(Cp) = v;
        } else if (MODE == 1) {
            float4 v = {scale * acc[i][0], scale * acc[i][1],
                        scale * acc[i][2], scale * acc[i][3]};
            *reinterpret_cast<float4*>(Cp) = v;
        } else {
            float4 o  = *reinterpret_cast<const float4*>(other + (size_t)row * N + col);
            float4 bb = *reinterpret_cast<const float4*>(bias + col);
            float4 v;
            v.x = fmaxf(fmaxf(scale * acc[i][0], o.x) + bb.x, 0.0f);
            v.y = fmaxf(fmaxf(scale * acc[i][1], o.y) + bb.y, 0.0f);
            v.z = fmaxf(fmaxf(scale * acc[i][2], o.z) + bb.z, 0.0f);
            v.w = fmaxf(fmaxf(scale * acc[i][3], o.w) + bb.w, 0.0f);
            *reinterpret_cast<float4*>(Cp) = v;
        }
    }
}

extern "C" void kernel_launch(void* const* d_in, const int* in_sizes, int n_in,
                              void* d_out, int out_size)
{
    // metadata order: x, weights, alpha, bias, s0, s1, s2, s3
    const float* x     = (const float*)d_in[0];   // [8192, 512]
    const float* W     = (const float*)d_in[1];   // [512, 512]
    const float* alpha = (const float*)d_in[2];   // [2]
    const float* bias  = (const float*)d_in[3];   // [512]
    const float* s0    = (const float*)d_in[4];   // [8192, 2048]
    const float* s1    = (const float*)d_in[5];   // [2048, 8192]
    const float* s2    = (const float*)d_in[6];   // [8192, 6144]
    const float* s3    = (const float*)d_in[7];   // [6144, 8192]
    float* out = (float*)d_out;                   // [8192, 512]

    float *pre, *t1, *t3, *low;
    cudaGetSymbolAddress((void**)&pre, g_pre);
    cudaGetSymbolAddress((void**)&t1,  g_t1);
    cudaGetSymbolAddress((void**)&t3,  g_t3);
    cudaGetSymbolAddress((void**)&low, g_low);

    dim3 blk(256);

    softmax2_kernel<<<1, 1>>>(alpha);

    // pre = x @ W                       [8192,512] = [8192,512]@[512,512]
    gemm_tile<0><<<dim3(DD / 64, NN / 128), blk>>>(x,  W,   pre, NN, DD, DD, 0, nullptr, nullptr);
    // t1 = s1 @ pre                     [2048,512] = [2048,8192]@[8192,512]
    gemm_tile<0><<<dim3(DD / 64, KF / 128), blk>>>(s1, pre, t1,  KF, DD, NN, 0, nullptr, nullptr);
    // t3 = s3 @ pre                     [6144,512] = [6144,8192]@[8192,512]
    gemm_tile<0><<<dim3(DD / 64, KH / 128), blk>>>(s3, pre, t3,  KH, DD, NN, 0, nullptr, nullptr);
    // low = a0 * (s0 @ t1)              [8192,512] = [8192,2048]@[2048,512]
    gemm_tile<1><<<dim3(DD / 64, NN / 128), blk>>>(s0, t1,  low, NN, DD, KF, 0, nullptr, nullptr);
    // out = relu(max(a1*(s2 @ t3), low) + bias)
    gemm_tile<2><<<dim3(DD / 64, NN / 128), blk>>>(s2, t3,  out, NN, DD, KH, 1, low, bias);
}

// round 3
// speedup vs baseline: 2.4117x; 2.4117x over previous
#include <cuda_runtime.h>
#include <cuda_bf16.h>
#include <cstdint>

// Shapes (fixed): N_NODES=8192, K_FRE=2048, K_HIGH=6144, D=512
#define NN 8192
#define KF 2048
#define KH 6144
#define DD 512

// ---------------- scratch (device globals) ----------------------------------
static __device__ __nv_bfloat16 g_WT_hi [DD * DD];
static __device__ __nv_bfloat16 g_WT_lo [DD * DD];
static __device__ __nv_bfloat16 g_preT_hi[DD * NN];
static __device__ __nv_bfloat16 g_preT_lo[DD * NN];
static __device__ __nv_bfloat16 g_t1T_hi [DD * KF];
static __device__ __nv_bfloat16 g_t1T_lo [DD * KF];
static __device__ __nv_bfloat16 g_t3T_hi [DD * KH];
static __device__ __nv_bfloat16 g_t3T_lo [DD * KH];
static __device__ float         g_low   [NN * DD];
static __device__ float         g_alpha [2];

// ---------------- PTX helpers (baseline ISA only: sm_80-era) -----------------
__device__ __forceinline__ uint32_t smem_u32(const void* p) {
    uint32_t a;
    asm("{ .reg .u64 t; cvta.to.shared.u64 t, %1; cvt.u32.u64 %0, t; }"
        : "=r"(a) : "l"(p));
    return a;
}
__device__ __forceinline__ void ldsm_x4(uint32_t r[4], uint32_t addr) {
    asm volatile("ldmatrix.sync.aligned.m8n8.x4.shared.b16 {%0,%1,%2,%3}, [%4];"
        : "=r"(r[0]), "=r"(r[1]), "=r"(r[2]), "=r"(r[3]) : "r"(addr));
}
__device__ __forceinline__ void mma16816(float c[4], const uint32_t a[4],
                                         uint32_t b0, uint32_t b1) {
    asm volatile("mma.sync.aligned.m16n8k16.row.col.f32.bf16.bf16.f32 "
        "{%0,%1,%2,%3}, {%4,%5,%6,%7}, {%8,%9}, {%0,%1,%2,%3};"
        : "+f"(c[0]), "+f"(c[1]), "+f"(c[2]), "+f"(c[3])
        : "r"(a[0]), "r"(a[1]), "r"(a[2]), "r"(a[3]), "r"(b0), "r"(b1));
}
__device__ __forceinline__ void cp16(uint32_t saddr, const void* g) {
    asm volatile("cp.async.cg.shared.global [%0], [%1], 16;" :: "r"(saddr), "l"(g));
}
#define CP_COMMIT()  asm volatile("cp.async.commit_group;" ::: "memory")
#define CP_WAIT(n)   asm volatile("cp.async.wait_group %0;" :: "n"(n) : "memory")

__device__ __forceinline__ uint32_t pk(__nv_bfloat16 a, __nv_bfloat16 b) {
    return (uint32_t)__bfloat16_as_ushort(a) | ((uint32_t)__bfloat16_as_ushort(b) << 16);
}

// ---------------- small kernels ----------------------------------------------
__global__ void softmax2_kernel(const float* __restrict__ alpha) {
    float a0 = alpha[0], a1 = alpha[1];
    float m = fmaxf(a0, a1);
    float e0 = expf(a0 - m), e1 = expf(a1 - m);
    float inv = 1.0f / (e0 + e1);
    g_alpha[0] = e0 * inv;
    g_alpha[1] = e1 * inv;
}

// W [512,512] -> WT hi/lo (WT[n][k] = W[k][n])
__global__ void wt_split_kernel(const float* __restrict__ W) {
    __shared__ float t[32][33];
    int bx = blockIdx.x * 32, by = blockIdx.y * 32;
    int tx = threadIdx.x, ty = threadIdx.y;
    t[ty][tx] = W[(size_t)(by + ty) * DD + bx + tx];
    __syncthreads();
    float v = t[tx][ty];
    int n = bx + ty, k = by + tx;
    __nv_bfloat16 h = __float2bfloat16(v);
    float lv = v - __bfloat162float(h);
    g_WT_hi[(size_t)n * DD + k] = h;
    g_WT_lo[(size_t)n * DD + k] = __float2bfloat16(lv);
}

// ---------------- split-bf16 mma.sync GEMM ------------------------------------
// C[M,512] = A[M,K](fp32) @ Bt[512,K]^T (bf16 hi/lo).
// CTA tile 128x128, 8 warps (2x4), warp tile 64x32, kc=64, 2-stage pipeline.
// MODE 0: write C^T split bf16 (CThi/CTlo, ld = ldT)
// MODE 1: Cf = alpha[aidx]*C
// MODE 2: Cf = relu(max(alpha[aidx]*C, other) + bias)
#define STAGE  65536
#define OFF_AH 0
#define OFF_AL 16384
#define OFF_BH 32768
#define OFF_BL 49152
#define SMEM_TOTAL (2 * STAGE)

template<int MODE>
__global__ __launch_bounds__(256, 1)
void gemm_mma(const float* __restrict__ A,
              const __nv_bfloat16* __restrict__ Bhi,
              const __nv_bfloat16* __restrict__ Blo,
              int M, int K, int ldT,
              float* __restrict__ Cf,
              __nv_bfloat16* __restrict__ CThi,
              __nv_bfloat16* __restrict__ CTlo,
              int aidx, const float* __restrict__ other,
              const float* __restrict__ bias)
{
    extern __shared__ char smem[];
    const uint32_t sb = smem_u32(smem);
    const int tid = threadIdx.x;
    const int wid = tid >> 5, lid = tid & 31;
    const int brow = blockIdx.y * 128, bcol = blockIdx.x * 128;
    const int wm = (wid >> 2) * 64, wn = (wid & 3) * 32;

    // loader indexing
    const int ldA_row = tid >> 4;            // 0..15 step -> +16 per r? (idx>>4 with idx=tid+r*256)
    const int ldA_seg = tid & 15;            // float4 seg within 64-elem row
    const int ldB_row = tid >> 3;            // 0..31
    const int ldB_seg = tid & 7;             // 16B seg within 128B row

    // ldmatrix per-lane geometry
    const int la_row = wm + (lid & 15);
    const int la_col = (lid >> 4) << 4;                 // 0 or 16 bytes
    const int axor   = (la_row & 7) << 4;
    const int lb_row = wn + (lid & 7) + ((lid >> 4) << 3);
    const int lb_col = ((lid >> 3) & 1) << 4;           // 0 or 16 bytes
    const int bxor   = (lb_row & 7) << 4;

    float acc[4][4][4];
    #pragma unroll
    for (int f = 0; f < 4; f++)
        #pragma unroll
        for (int j = 0; j < 4; j++)
            #pragma unroll
            for (int q = 0; q < 4; q++) acc[f][j][q] = 0.0f;

    const int nt = K >> 6;
    float4 av[8];

    // ---- loaders (inline) ----
    #define LDG_A(kt) do { \
        _Pragma("unroll") \
        for (int r = 0; r < 8; r++) { \
            int row = ldA_row + r * 16; \
            av[r] = *reinterpret_cast<const float4*>( \
                A + (size_t)(brow + row) * K + (kt) + (ldA_seg << 2)); \
        } } while (0)

    #define STS_A(base_u) do { \
        _Pragma("unroll") \
        for (int r = 0; r < 8; r++) { \
            int row = ldA_row + r * 16; \
            int colb = ldA_seg << 3; \
            uint32_t off = (uint32_t)(row * 128 + (colb ^ ((row & 7) << 4))); \
            float4 v = av[r]; \
            __nv_bfloat16 h0 = __float2bfloat16(v.x); \
            __nv_bfloat16 h1 = __float2bfloat16(v.y); \
            __nv_bfloat16 h2 = __float2bfloat16(v.z); \
            __nv_bfloat16 h3 = __float2bfloat16(v.w); \
            __nv_bfloat16 l0 = __float2bfloat16(v.x - __bfloat162float(h0)); \
            __nv_bfloat16 l1 = __float2bfloat16(v.y - __bfloat162float(h1)); \
            __nv_bfloat16 l2 = __float2bfloat16(v.z - __bfloat162float(h2)); \
            __nv_bfloat16 l3 = __float2bfloat16(v.w - __bfloat162float(h3)); \
            *reinterpret_cast<uint2*>(smem + ((base_u) - sb) + OFF_AH + off) = \
                make_uint2(pk(h0, h1), pk(h2, h3)); \
            *reinterpret_cast<uint2*>(smem + ((base_u) - sb) + OFF_AL + off) = \
                make_uint2(pk(l0, l1), pk(l2, l3)); \
        } } while (0)

    #define CPA_B(base_u, kt) do { \
        _Pragma("unroll") \
        for (int r = 0; r < 4; r++) { \
            int row = ldB_row + r * 32; \
            int colb = ldB_seg << 4; \
            uint32_t off = (uint32_t)(row * 128 + (colb ^ ((row & 7) << 4))); \
            size_t g = (size_t)(bcol + row) * K + (kt) + (ldB_seg << 3); \
            cp16((base_u) + OFF_BH + off, Bhi + g); \
            cp16((base_u) + OFF_BL + off, Blo + g); \
        } } while (0)

    // ---- prologue: stage 0 ----
    LDG_A(0);
    CPA_B(sb, 0);
    CP_COMMIT();
    STS_A(sb);

    for (int it = 0; it < nt; it++) {
        const uint32_t cbase = sb + (uint32_t)(it & 1) * STAGE;
        const uint32_t nbase = sb + (uint32_t)((it + 1) & 1) * STAGE;
        const bool pf = (it + 1 < nt);
        if (pf) {
            LDG_A((it + 1) << 6);
            CPA_B(nbase, (it + 1) << 6);
            CP_COMMIT();
            CP_WAIT(1);
        } else {
            CP_WAIT(0);
        }
        __syncthreads();

        // ---- compute this stage: 4 k16 steps ----
        #pragma unroll
        for (int ks = 0; ks < 4; ks++) {
            uint32_t ah[4][4], al[4][4];
            #pragma unroll
            for (int f = 0; f < 4; f++) {
                uint32_t aoff = (uint32_t)((la_row + f * 16) * 128 +
                                 ((la_col + ks * 32) ^ axor));
                ldsm_x4(ah[f], cbase + OFF_AH + aoff);
                ldsm_x4(al[f], cbase + OFF_AL + aoff);
            }
            uint32_t bh[2][4], bl[2][4];
            #pragma unroll
            for (int p = 0; p < 2; p++) {
                uint32_t boff = (uint32_t)((lb_row + p * 16) * 128 +
                                 ((lb_col + ks * 32) ^ bxor));
                ldsm_x4(bh[p], cbase + OFF_BH + boff);
                ldsm_x4(bl[p], cbase + OFF_BL + boff);
            }
            #pragma unroll
            for (int f = 0; f < 4; f++)
                #pragma unroll
                for (int p = 0; p < 2; p++)
                    #pragma unroll
                    for (int h = 0; h < 2; h++) {
                        float* c = acc[f][p * 2 + h];
                        mma16816(c, ah[f], bh[p][h * 2], bh[p][h * 2 + 1]);
                        mma16816(c, al[f], bh[p][h * 2], bh[p][h * 2 + 1]);
                        mma16816(c, ah[f], bl[p][h * 2], bl[p][h * 2 + 1]);
                    }
        }

        if (pf) STS_A(nbase);
        __syncthreads();
    }

    // ---- epilogue ----
    const int g = lid >> 2, t = lid & 3;
    if (MODE == 0) {
        #pragma unroll
        for (int f = 0; f < 4; f++) {
            const int m0 = brow + wm + f * 16 + g;
            #pragma unroll
            for (int j = 0; j < 4; j++) {
                const int c0 = bcol + wn + j * 8 + 2 * t;
                #pragma unroll
                for (int q = 0; q < 4; q++) {
                    float v = acc[f][j][q];
                    int cc = c0 + (q & 1);
                    int mm = m0 + (q >> 1) * 8;
                    __nv_bfloat16 h = __float2bfloat16(v);
                    float lv = v - __bfloat162float(h);
                    CThi[(size_t)cc * ldT + mm] = h;
                    CTlo[(size_t)cc * ldT + mm] = __float2bfloat16(lv);
                }
            }
        }
    } else {
        const float as = g_alpha[aidx];
        #pragma unroll
        for (int f = 0; f < 4; f++) {
            const int m0 = brow + wm + f * 16 + g;
            #pragma unroll
            for (int j = 0; j < 4; j++) {
                const int c0 = bcol + wn + j * 8 + 2 * t;
                if (MODE == 1) {
                    float2 v0 = make_float2(as * acc[f][j][0], as * acc[f][j][1]);
                    float2 v1 = make_float2(as * acc[f][j][2], as * acc[f][j][3]);
                    *reinterpret_cast<float2*>(Cf + (size_t)m0 * DD + c0) = v0;
                    *reinterpret_cast<float2*>(Cf + (size_t)(m0 + 8) * DD + c0) = v1;
                } else {
                    float2 o0 = *reinterpret_cast<const float2*>(other + (size_t)m0 * DD + c0);
                    float2 o1 = *reinterpret_cast<const float2*>(other + (size_t)(m0 + 8) * DD + c0);
                    float2 bb = *reinterpret_cast<const float2*>(bias + c0);
                    float2 v0, v1;
                    v0.x = fmaxf(fmaxf(as * acc[f][j][0], o0.x) + bb.x, 0.0f);
                    v0.y = fmaxf(fmaxf(as * acc[f][j][1], o0.y) + bb.y, 0.0f);
                    v1.x = fmaxf(fmaxf(as * acc[f][j][2], o1.x) + bb.x, 0.0f);
                    v1.y = fmaxf(fmaxf(as * acc[f][j][3], o1.y) + bb.y, 0.0f);
                    *reinterpret_cast<float2*>(Cf + (size_t)m0 * DD + c0) = v0;
                    *reinterpret_cast<float2*>(Cf + (size_t)(m0 + 8) * DD + c0) = v1;
                }
            }
        }
    }
    #undef LDG_A
    #undef STS_A
    #undef CPA_B
}

// ---------------- host launch --------------------------------------------------
extern "C" void kernel_launch(void* const* d_in, const int* in_sizes, int n_in,
                              void* d_out, int out_size)
{
    const float* x     = (const float*)d_in[0];
    const float* W     = (const float*)d_in[1];
    const float* alpha = (const float*)d_in[2];
    const float* bias  = (const float*)d_in[3];
    const float* s0    = (const float*)d_in[4];
    const float* s1    = (const float*)d_in[5];
    const float* s2    = (const float*)d_in[6];
    const float* s3    = (const float*)d_in[7];
    float* out = (float*)d_out;

    __nv_bfloat16 *WTh, *WTl, *pTh, *pTl, *t1h, *t1l, *t3h, *t3l;
    float* low;
    cudaGetSymbolAddress((void**)&WTh, g_WT_hi);
    cudaGetSymbolAddress((void**)&WTl, g_WT_lo);
    cudaGetSymbolAddress((void**)&pTh, g_preT_hi);
    cudaGetSymbolAddress((void**)&pTl, g_preT_lo);
    cudaGetSymbolAddress((void**)&t1h, g_t1T_hi);
    cudaGetSymbolAddress((void**)&t1l, g_t1T_lo);
    cudaGetSymbolAddress((void**)&t3h, g_t3T_hi);
    cudaGetSymbolAddress((void**)&t3l, g_t3T_lo);
    cudaGetSymbolAddress((void**)&low, g_low);

    static bool attr_done = false;
    if (!attr_done) {
        cudaFuncSetAttribute(gemm_mma<0>, cudaFuncAttributeMaxDynamicSharedMemorySize, SMEM_TOTAL);
        cudaFuncSetAttribute(gemm_mma<1>, cudaFuncAttributeMaxDynamicSharedMemorySize, SMEM_TOTAL);
        cudaFuncSetAttribute(gemm_mma<2>, cudaFuncAttributeMaxDynamicSharedMemorySize, SMEM_TOTAL);
        attr_done = true;
    }

    softmax2_kernel<<<1, 1>>>(alpha);
    wt_split_kernel<<<dim3(16, 16), dim3(32, 32)>>>(W);

    // pre^T = (x @ W)^T, split bf16
    gemm_mma<0><<<dim3(4, NN / 128), 256, SMEM_TOTAL>>>(
        x, WTh, WTl, NN, DD, NN, nullptr, pTh, pTl, 0, nullptr, nullptr);
    // t1^T = (s1 @ pre)^T
    gemm_mma<0><<<dim3(4, KF / 128), 256, SMEM_TOTAL>>>(
        s1, pTh, pTl, KF, NN, KF, nullptr, t1h, t1l, 0, nullptr, nullptr);
    // t3^T = (s3 @ pre)^T
    gemm_mma<0><<<dim3(4, KH / 128), 256, SMEM_TOTAL>>>(
        s3, pTh, pTl, KH, NN, KH, nullptr, t3h, t3l, 0, nullptr, nullptr);
    // low = a0 * (s0 @ t1)
    gemm_mma<1><<<dim3(4, NN / 128), 256, SMEM_TOTAL>>>(
        s0, t1h, t1l, NN, KF, 0, low, nullptr, nullptr, 0, nullptr, nullptr);
    // out = relu(max(a1*(s2 @ t3), low) + bias)
    gemm_mma<2><<<dim3(4, NN / 128), 256, SMEM_TOTAL>>>(
        s2, t3h, t3l, NN, KH, 0, out, nullptr, nullptr, 1, low, bias);
}

// round 4
// speedup vs baseline: 3.3390x; 1.3845x over previous
#include <cuda_runtime.h>
#include <cuda_bf16.h>
#include <cstdint>

// Shapes (fixed): N_NODES=8192, K_FRE=2048, K_HIGH=6144, D=512
#define NN 8192
#define KF 2048
#define KH 6144
#define DD 512

// ---------------- scratch (device globals) ----------------------------------
static __device__ __nv_bfloat16 g_WT_hi [DD * DD];
static __device__ __nv_bfloat16 g_WT_lo [DD * DD];
static __device__ __nv_bfloat16 g_preT_hi[DD * NN];
static __device__ __nv_bfloat16 g_preT_lo[DD * NN];
static __device__ __nv_bfloat16 g_t1T_hi [DD * KF];
static __device__ __nv_bfloat16 g_t1T_lo [DD * KF];
static __device__ __nv_bfloat16 g_t3T_hi [DD * KH];
static __device__ __nv_bfloat16 g_t3T_lo [DD * KH];
static __device__ float         g_low   [NN * DD];
static __device__ float         g_alpha [2];

// ---------------- PTX helpers (baseline ISA only) -----------------------------
__device__ __forceinline__ uint32_t smem_u32(const void* p) {
    uint32_t a;
    asm("{ .reg .u64 t; cvta.to.shared.u64 t, %1; cvt.u32.u64 %0, t; }"
        : "=r"(a) : "l"(p));
    return a;
}
__device__ __forceinline__ void ldsm_x4(uint32_t r[4], uint32_t addr) {
    asm volatile("ldmatrix.sync.aligned.m8n8.x4.shared.b16 {%0,%1,%2,%3}, [%4];"
        : "=r"(r[0]), "=r"(r[1]), "=r"(r[2]), "=r"(r[3]) : "r"(addr));
}
__device__ __forceinline__ void mma16816(float c[4], const uint32_t a[4],
                                         uint32_t b0, uint32_t b1) {
    asm volatile("mma.sync.aligned.m16n8k16.row.col.f32.bf16.bf16.f32 "
        "{%0,%1,%2,%3}, {%4,%5,%6,%7}, {%8,%9}, {%0,%1,%2,%3};"
        : "+f"(c[0]), "+f"(c[1]), "+f"(c[2]), "+f"(c[3])
        : "r"(a[0]), "r"(a[1]), "r"(a[2]), "r"(a[3]), "r"(b0), "r"(b1));
}
__device__ __forceinline__ void cp16(uint32_t saddr, const void* g) {
    asm volatile("cp.async.cg.shared.global [%0], [%1], 16;" :: "r"(saddr), "l"(g));
}
#define CP_COMMIT()  asm volatile("cp.async.commit_group;" ::: "memory")
#define CP_WAIT1()   asm volatile("cp.async.wait_group 1;" ::: "memory")
#define CP_WAIT0()   asm volatile("cp.async.wait_group 0;" ::: "memory")

__device__ __forceinline__ uint32_t pk(__nv_bfloat16 a, __nv_bfloat16 b) {
    return (uint32_t)__bfloat16_as_ushort(a) | ((uint32_t)__bfloat16_as_ushort(b) << 16);
}

// ---------------- small kernels ------------------------------------------------
__global__ void softmax2_kernel(const float* __restrict__ alpha) {
    float a0 = alpha[0], a1 = alpha[1];
    float m = fmaxf(a0, a1);
    float e0 = expf(a0 - m), e1 = expf(a1 - m);
    float inv = 1.0f / (e0 + e1);
    g_alpha[0] = e0 * inv;
    g_alpha[1] = e1 * inv;
}

__global__ void wt_split_kernel(const float* __restrict__ W) {
    __shared__ float t[32][33];
    int bx = blockIdx.x * 32, by = blockIdx.y * 32;
    int tx = threadIdx.x, ty = threadIdx.y;
    t[ty][tx] = W[(size_t)(by + ty) * DD + bx + tx];
    __syncthreads();
    float v = t[tx][ty];
    int n = bx + ty, k = by + tx;
    __nv_bfloat16 h = __float2bfloat16(v);
    float lv = v - __bfloat162float(h);
    g_WT_hi[(size_t)n * DD + k] = h;
    g_WT_lo[(size_t)n * DD + k] = __float2bfloat16(lv);
}

// ---------------- split-bf16 mma.sync GEMM --------------------------------------
// C[M,512] = A[M,K](fp32) @ Bt[512,K]^T (bf16 hi/lo).
// CTA 128x128, 512 threads (16 warps, 4x4), warp tile 32x32, kc=64, 3-stage.
// MODE 0: write C^T split bf16 into (CThi1,CTlo1), ld1
// MODE 3: rows < M1 -> (CThi1,CTlo1,ld1); rows >= M1 -> (CThi2,CTlo2,ld2), row-M1
// MODE 1: Cf = alpha[aidx]*C
// MODE 2: Cf = relu(max(alpha[aidx]*C, other) + bias)
#define STAGE  65536
#define OFF_AH 0
#define OFF_AL 16384
#define OFF_BH 32768
#define OFF_BL 49152
#define NSTAGE 3
#define SMEM_TOTAL (NSTAGE * STAGE)

template<int MODE>
__global__ __launch_bounds__(512, 1)
void gemm_mma(const float* __restrict__ A1, const float* __restrict__ A2, int M1,
              const __nv_bfloat16* __restrict__ Bhi,
              const __nv_bfloat16* __restrict__ Blo,
              int K,
              float* __restrict__ Cf,
              __nv_bfloat16* __restrict__ CThi1, __nv_bfloat16* __restrict__ CTlo1, int ld1,
              __nv_bfloat16* __restrict__ CThi2, __nv_bfloat16* __restrict__ CTlo2, int ld2,
              int aidx, const float* __restrict__ other,
              const float* __restrict__ bias)
{
    extern __shared__ char smem[];
    const uint32_t sb = smem_u32(smem);
    const int tid = threadIdx.x;
    const int wid = tid >> 5, lid = tid & 31;
    const int brow = blockIdx.y * 128, bcol = blockIdx.x * 128;
    const int wm = (wid >> 2) * 32, wn = (wid & 3) * 32;

    // per-CTA A base (MODE 3 picks s1 or s3)
    const float* Abase;
    if (MODE == 3 && brow >= M1) Abase = A2 + (size_t)(brow - M1) * K;
    else                         Abase = A1 + (size_t)brow * K;

    // loader indexing (512 threads)
    const int ldA_row = tid >> 4;   // +128 per r (r<4): rows 0..127 via idx>>4
    const int ldA_seg = tid & 15;
    const int ldB_row = tid >> 3;   // r<2: rows 0..127 via idx>>3
    const int ldB_seg = tid & 7;

    // ldmatrix lane geometry (rows of 128B, XOR swizzle)
    const int la_row = wm + (lid & 15);
    const int la_col = (lid >> 4) << 4;
    const int axor   = (la_row & 7) << 4;
    const int lb_row = wn + (lid & 7) + ((lid >> 4) << 3);
    const int lb_col = ((lid >> 3) & 1) << 4;
    const int bxor   = (lb_row & 7) << 4;

    float acc[2][4][4];
    #pragma unroll
    for (int f = 0; f < 2; f++)
        #pragma unroll
        for (int j = 0; j < 4; j++)
            #pragma unroll
            for (int q = 0; q < 4; q++) acc[f][j][q] = 0.0f;

    const int nt = K >> 6;
    float4 av[4];

    #define LDG_A(kt) do { \
        _Pragma("unroll") \
        for (int r = 0; r < 4; r++) { \
            int idx = tid + (r << 9); \
            int row = idx >> 4, seg = idx & 15; \
            av[r] = *reinterpret_cast<const float4*>( \
                Abase + (size_t)row * K + (kt) + (seg << 2)); \
        } } while (0)

    #define STS_A(sidx) do { \
        char* bse = smem + (size_t)(sidx) * STAGE; \
        _Pragma("unroll") \
        for (int r = 0; r < 4; r++) { \
            int idx = tid + (r << 9); \
            int row = idx >> 4, seg = idx & 15; \
            uint32_t off = (uint32_t)(row * 128 + ((seg << 3) ^ ((row & 7) << 4))); \
            float4 v = av[r]; \
            __nv_bfloat16 h0 = __float2bfloat16(v.x); \
            __nv_bfloat16 h1 = __float2bfloat16(v.y); \
            __nv_bfloat16 h2 = __float2bfloat16(v.z); \
            __nv_bfloat16 h3 = __float2bfloat16(v.w); \
            __nv_bfloat16 l0 = __float2bfloat16(v.x - __bfloat162float(h0)); \
            __nv_bfloat16 l1 = __float2bfloat16(v.y - __bfloat162float(h1)); \
            __nv_bfloat16 l2 = __float2bfloat16(v.z - __bfloat162float(h2)); \
            __nv_bfloat16 l3 = __float2bfloat16(v.w - __bfloat162float(h3)); \
            *reinterpret_cast<uint2*>(bse + OFF_AH + off) = make_uint2(pk(h0,h1), pk(h2,h3)); \
            *reinterpret_cast<uint2*>(bse + OFF_AL + off) = make_uint2(pk(l0,l1), pk(l2,l3)); \
        } } while (0)

    #define CPA_B(sidx, kt) do { \
        uint32_t bse = sb + (uint32_t)(sidx) * STAGE; \
        _Pragma("unroll") \
        for (int r = 0; r < 2; r++) { \
            int idx = tid + (r << 9); \
            int row = idx >> 3, seg = idx & 7; \
            uint32_t off = (uint32_t)(row * 128 + ((seg << 4) ^ ((row & 7) << 4))); \
            size_t g = (size_t)(bcol + row) * K + (kt) + (seg << 3); \
            cp16(bse + OFF_BH + off, Bhi + g); \
            cp16(bse + OFF_BL + off, Blo + g); \
        } } while (0)

    // ---- prologue: fill stages 0,1 ----
    LDG_A(0);
    CPA_B(0, 0); CP_COMMIT();
    STS_A(0);
    LDG_A(64);
    CPA_B(1, 64); CP_COMMIT();
    STS_A(1);

    int sld = 2;       // next stage slot to fill
    for (int it = 0; it < nt; it++) {
        const int cs = it % NSTAGE;
        const uint32_t cbase = sb + (uint32_t)cs * STAGE;
        const bool pf = (it + 2 < nt);
        if (pf) LDG_A((it + 2) << 6);
        if (pf) { CP_WAIT1(); } else { CP_WAIT0(); }
        __syncthreads();

        #pragma unroll
        for (int ks = 0; ks < 4; ks++) {
            uint32_t ah[2][4], al[2][4], bh[2][4], bl[2][4];
            #pragma unroll
            for (int f = 0; f < 2; f++) {
                uint32_t aoff = (uint32_t)((la_row + f * 16) * 128 +
                                 ((la_col + ks * 32) ^ axor));
                ldsm_x4(ah[f], cbase + OFF_AH + aoff);
                ldsm_x4(al[f], cbase + OFF_AL + aoff);
            }
            #pragma unroll
            for (int p = 0; p < 2; p++) {
                uint32_t boff = (uint32_t)((lb_row + p * 16) * 128 +
                                 ((lb_col + ks * 32) ^ bxor));
                ldsm_x4(bh[p], cbase + OFF_BH + boff);
                ldsm_x4(bl[p], cbase + OFF_BL + boff);
            }
            #pragma unroll
            for (int f = 0; f < 2; f++)
                #pragma unroll
                for (int p = 0; p < 2; p++)
                    #pragma unroll
                    for (int h = 0; h < 2; h++) {
                        float* c = acc[f][p * 2 + h];
                        mma16816(c, ah[f], bh[p][h * 2], bh[p][h * 2 + 1]);
                        mma16816(c, al[f], bh[p][h * 2], bh[p][h * 2 + 1]);
                        mma16816(c, ah[f], bl[p][h * 2], bl[p][h * 2 + 1]);
                    }
        }

        if (pf) {
            STS_A(sld);
            CPA_B(sld, (it + 2) << 6);
            CP_COMMIT();
            sld = (sld + 1) % NSTAGE;
        }
    }

    // ---- epilogue ----
    const int g = lid >> 2, t = lid & 3;
    if (MODE == 0 || MODE == 3) {
        #pragma unroll
        for (int f = 0; f < 2; f++) {
            const int m0 = brow + wm + f * 16 + g;
            #pragma unroll
            for (int j = 0; j < 4; j++) {
                const int c0 = bcol + wn + j * 8 + 2 * t;
                #pragma unroll
                for (int q = 0; q < 4; q++) {
                    float v = acc[f][j][q];
                    int cc = c0 + (q & 1);
                    int mm = m0 + (q >> 1) * 8;
                    __nv_bfloat16 h = __float2bfloat16(v);
                    __nv_bfloat16 l = __float2bfloat16(v - __bfloat162float(h));
                    if (MODE == 0 || mm < M1) {
                        CThi1[(size_t)cc * ld1 + mm] = h;
                        CTlo1[(size_t)cc * ld1 + mm] = l;
                    } else {
                        CThi2[(size_t)cc * ld2 + (mm - M1)] = h;
                        CTlo2[(size_t)cc * ld2 + (mm - M1)] = l;
                    }
                }
            }
        }
    } else {
        const float as = g_alpha[aidx];
        #pragma unroll
        for (int f = 0; f < 2; f++) {
            const int m0 = brow + wm + f * 16 + g;
            #pragma unroll
            for (int j = 0; j < 4; j++) {
                const int c0 = bcol + wn + j * 8 + 2 * t;
                if (MODE == 1) {
                    float2 v0 = make_float2(as * acc[f][j][0], as * acc[f][j][1]);
                    float2 v1 = make_float2(as * acc[f][j][2], as * acc[f][j][3]);
                    *reinterpret_cast<float2*>(Cf + (size_t)m0 * DD + c0) = v0;
                    *reinterpret_cast<float2*>(Cf + (size_t)(m0 + 8) * DD + c0) = v1;
                } else {
                    float2 o0 = *reinterpret_cast<const float2*>(other + (size_t)m0 * DD + c0);
                    float2 o1 = *reinterpret_cast<const float2*>(other + (size_t)(m0 + 8) * DD + c0);
                    float2 bb = *reinterpret_cast<const float2*>(bias + c0);
                    float2 v0, v1;
                    v0.x = fmaxf(fmaxf(as * acc[f][j][0], o0.x) + bb.x, 0.0f);
                    v0.y = fmaxf(fmaxf(as * acc[f][j][1], o0.y) + bb.y, 0.0f);
                    v1.x = fmaxf(fmaxf(as * acc[f][j][2], o1.x) + bb.x, 0.0f);
                    v1.y = fmaxf(fmaxf(as * acc[f][j][3], o1.y) + bb.y, 0.0f);
                    *reinterpret_cast<float2*>(Cf + (size_t)m0 * DD + c0) = v0;
                    *reinterpret_cast<float2*>(Cf + (size_t)(m0 + 8) * DD + c0) = v1;
                }
            }
        }
    }
    #undef LDG_A
    #undef STS_A
    #undef CPA_B
}

// ---------------- host launch ----------------------------------------------------
extern "C" void kernel_launch(void* const* d_in, const int* in_sizes, int n_in,
                              void* d_out, int out_size)
{
    const float* x     = (const float*)d_in[0];
    const float* W     = (const float*)d_in[1];
    const float* alpha = (const float*)d_in[2];
    const float* bias  = (const float*)d_in[3];
    const float* s0    = (const float*)d_in[4];
    const float* s1    = (const float*)d_in[5];
    const float* s2    = (const float*)d_in[6];
    const float* s3    = (const float*)d_in[7];
    float* out = (float*)d_out;

    __nv_bfloat16 *WTh, *WTl, *pTh, *pTl, *t1h, *t1l, *t3h, *t3l;
    float* low;
    cudaGetSymbolAddress((void**)&WTh, g_WT_hi);
    cudaGetSymbolAddress((void**)&WTl, g_WT_lo);
    cudaGetSymbolAddress((void**)&pTh, g_preT_hi);
    cudaGetSymbolAddress((void**)&pTl, g_preT_lo);
    cudaGetSymbolAddress((void**)&t1h, g_t1T_hi);
    cudaGetSymbolAddress((void**)&t1l, g_t1T_lo);
    cudaGetSymbolAddress((void**)&t3h, g_t3T_hi);
    cudaGetSymbolAddress((void**)&t3l, g_t3T_lo);
    cudaGetSymbolAddress((void**)&low, g_low);

    static bool attr_done = false;
    if (!attr_done) {
        cudaFuncSetAttribute(gemm_mma<0>, cudaFuncAttributeMaxDynamicSharedMemorySize, SMEM_TOTAL);
        cudaFuncSetAttribute(gemm_mma<1>, cudaFuncAttributeMaxDynamicSharedMemorySize, SMEM_TOTAL);
        cudaFuncSetAttribute(gemm_mma<2>, cudaFuncAttributeMaxDynamicSharedMemorySize, SMEM_TOTAL);
        cudaFuncSetAttribute(gemm_mma<3>, cudaFuncAttributeMaxDynamicSharedMemorySize, SMEM_TOTAL);
        attr_done = true;
    }

    softmax2_kernel<<<1, 1>>>(alpha);
    wt_split_kernel<<<dim3(16, 16), dim3(32, 32)>>>(W);

    // pre^T = (x @ W)^T (split bf16)            grid 4x64 = 256
    gemm_mma<0><<<dim3(4, NN / 128), 512, SMEM_TOTAL>>>(
        x, nullptr, NN, WTh, WTl, DD,
        nullptr, pTh, pTl, NN, nullptr, nullptr, 0, 0, nullptr, nullptr);
    // merged: t1^T (rows<2048 from s1) + t3^T (rows>=2048 from s3)   grid 4x64 = 256
    gemm_mma<3><<<dim3(4, NN / 128), 512, SMEM_TOTAL>>>(
        s1, s3, KF, pTh, pTl, NN,
        nullptr, t1h, t1l, KF, t3h, t3l, KH, 0, nullptr, nullptr);
    // low = a0 * (s0 @ t1)                       grid 4x64 = 256
    gemm_mma<1><<<dim3(4, NN / 128), 512, SMEM_TOTAL>>>(
        s0, nullptr, NN, t1h, t1l, KF,
        low, nullptr, nullptr, 0, nullptr, nullptr, 0, 0, nullptr, nullptr);
    // out = relu(max(a1*(s2 @ t3), low) + bias)  grid 4x64 = 256
    gemm_mma<2><<<dim3(4, NN / 128), 512, SMEM_TOTAL>>>(
        s2, nullptr, NN, t3h, t3l, KH,
        out, nullptr, nullptr, 0, nullptr, nullptr, 1, 1, low, bias);
}